// round 6
// baseline (speedup 1.0000x reference)
#include <cuda_runtime.h>
#include <cstdint>

// Problem constants
#define BB 8
#define NN 2048
#define DD 128
#define HH 4
#define DH 32
#define NBH 32          // B*H
#define BN 16384        // B*N

// ---------------- device scratch ----------------
__device__ float g_h[NBH * NN * DH];          // (b,h,n,dh) = 2M floats
__device__ float g_src[NBH * NN];
__device__ float g_dst[NBH * NN];
__device__ float g_E [NBH * NN];              // exp(src)
__device__ float g_E5[NBH * NN];              // exp(0.2*src)
__device__ float g_F [NBH * NN];              // exp(dst)
__device__ float g_F5[NBH * NN];              // exp(0.2*dst)
__device__ float g_att[BN * DD];              // attention output, (b,n,d)

// packed f32x2 helpers: accumulator stays resident as b64
#define FFMA2(accum, a64, b64) \
    asm("fma.rn.f32x2 %0, %1, %2, %0;" : "+l"(accum) : "l"(a64), "l"(b64))

__device__ __forceinline__ unsigned long long dup_f32(float v) {
    unsigned long long r;
    asm("mov.b64 %0, {%1, %1};" : "=l"(r) : "f"(v));
    return r;
}
__device__ __forceinline__ void unpack2(unsigned long long p, float &lo, float &hi) {
    asm("mov.b64 {%0, %1}, %2;" : "=f"(lo), "=f"(hi) : "l"(p));
}

// ---------------- Kernel 1: h = x @ W^T, stored (b,h,n,dh) ----------------
// grid 1024, block 128. Each block: 16 rows (b,n), each thread one output col.
__global__ __launch_bounds__(128) void k1_proj(const float* __restrict__ x,
                                               const float* __restrict__ W) {
    __shared__ __align__(16) float sxt[128][20];   // [k][row], 80B rows (16B aligned)
    __shared__ float sW[32][129];                  // [k][d'], padded

    const int t = threadIdx.x;
    const int row0 = blockIdx.x * 16;
    const float* xb = x + (size_t)row0 * DD;
    const uint32_t sxt_addr = (uint32_t)__cvta_generic_to_shared(&sxt[0][0]);

    #pragma unroll
    for (int m = 0; m < 16; ++m) sxt[t][m] = xb[m * DD + t];   // coalesced

    unsigned long long acc[8];
    #pragma unroll
    for (int rp = 0; rp < 8; ++rp) acc[rp] = 0ull;

    for (int kt = 0; kt < DD; kt += 32) {
        __syncthreads();
        // stage W[d'][kt..kt+31] -> sW[k][d']
        #pragma unroll
        for (int m = 0; m < 32; ++m) {
            int lin = t + 128 * m;            // 0..4095
            int dp = lin >> 5, k = lin & 31;
            sW[k][dp] = W[dp * DD + kt + k];
        }
        __syncthreads();
        #pragma unroll
        for (int k = 0; k < 32; ++k) {
            unsigned long long wb = dup_f32(sW[k][t]);
            uint32_t ra = sxt_addr + (uint32_t)(kt + k) * 80u;
            unsigned long long x0, x1, x2, x3, x4, x5, x6, x7;
            asm("ld.shared.v2.b64 {%0,%1}, [%2];"    : "=l"(x0), "=l"(x1) : "r"(ra));
            asm("ld.shared.v2.b64 {%0,%1}, [%2+16];" : "=l"(x2), "=l"(x3) : "r"(ra));
            asm("ld.shared.v2.b64 {%0,%1}, [%2+32];" : "=l"(x4), "=l"(x5) : "r"(ra));
            asm("ld.shared.v2.b64 {%0,%1}, [%2+48];" : "=l"(x6), "=l"(x7) : "r"(ra));
            FFMA2(acc[0], x0, wb);
            FFMA2(acc[1], x1, wb);
            FFMA2(acc[2], x2, wb);
            FFMA2(acc[3], x3, wb);
            FFMA2(acc[4], x4, wb);
            FFMA2(acc[5], x5, wb);
            FFMA2(acc[6], x6, wb);
            FFMA2(acc[7], x7, wb);
        }
    }

    const int hh = t >> 5, dh = t & 31;
    #pragma unroll
    for (int rp = 0; rp < 8; ++rp) {
        float a0, a1;
        unpack2(acc[rp], a0, a1);
        int bn = row0 + 2 * rp;
        int b = bn >> 11, n = bn & 2047;
        size_t base = (((size_t)b * HH + hh) * NN + n) * DH + dh;
        g_h[base]      = a0;
        g_h[base + DH] = a1;   // n+1, same b (16-row blocks aligned)
    }
}

// ---------------- Kernel 2: src/dst dots + exps ----------------
__global__ __launch_bounds__(256) void k2_srcdst(const float* __restrict__ a_src,
                                                 const float* __restrict__ a_dst) {
    int idx = blockIdx.x * 256 + threadIdx.x;   // = bh*N + n, < 65536
    int hh = (idx >> 11) & 3;
    const float* hrow = g_h + (size_t)idx * DH;
    const float* as = a_src + hh * DH;
    const float* ad = a_dst + hh * DH;
    float s = 0.f, d = 0.f;
    #pragma unroll
    for (int k = 0; k < DH; ++k) {
        float hv = hrow[k];
        s += hv * as[k];
        d += hv * ad[k];
    }
    g_src[idx] = s;
    g_dst[idx] = d;
    g_E [idx] = __expf(s);
    g_E5[idx] = __expf(0.2f * s);
    g_F [idx] = __expf(d);
    g_F5[idx] = __expf(0.2f * d);
}

// ---------------- Kernel 3: fused attention (the big one) ----------------
// grid (N/64, B*H), block 256 (8 warps). Warp w owns rows i0+8w..i0+8w+7.
// Each lane owns dh = lane; rows packed in pairs via f32x2 with b64-resident acc.
#define TJ 64
__global__ __launch_bounds__(256) void k3_attn(const float* __restrict__ adj) {
    __shared__ float sh_h[TJ * DH];                      // 8 KB
    __shared__ float sh_dst[TJ], sh_F[TJ], sh_F5[TJ];
    __shared__ float sh_adj[64 * TJ];                    // 16 KB
    __shared__ __align__(16) float2 sh_w[8][TJ][4];      // 16 KB

    const int bh = blockIdx.y;
    const int i0 = blockIdx.x * 64;
    const int tid = threadIdx.x;
    const int warp = tid >> 5, lane = tid & 31;
    const int rbase = warp * 8;                // block-local first row of this warp

    // per-row constants (uniform per warp)
    float rs[8], rE[8], rE5[8];
    {
        int gb = bh * NN + i0 + rbase;
        #pragma unroll
        for (int r = 0; r < 8; ++r) {
            rs[r]  = g_src[gb + r];
            rE[r]  = g_E [gb + r];
            rE5[r] = g_E5[gb + r];
        }
    }

    unsigned long long acc[4];
    #pragma unroll
    for (int rp = 0; rp < 4; ++rp) acc[rp] = 0ull;
    float ls[8];
    #pragma unroll
    for (int r = 0; r < 8; ++r) ls[r] = 0.f;

    const float* hbh = g_h + (size_t)bh * NN * DH;
    const int jo = bh * NN;
    const uint32_t wbase = (uint32_t)__cvta_generic_to_shared(&sh_w[warp][0][0]);

    for (int jt = 0; jt < NN; jt += TJ) {
        __syncthreads();
        // --- stage tiles ---
        {
            const float4* hsrc = (const float4*)(hbh + (size_t)jt * DH);
            float4* hdst = (float4*)sh_h;
            hdst[tid]       = hsrc[tid];
            hdst[tid + 256] = hsrc[tid + 256];
        }
        if (tid < TJ) {
            int jj = jo + jt + tid;
            sh_dst[tid] = g_dst[jj];
            sh_F [tid] = g_F [jj];
            sh_F5[tid] = g_F5[jj];
        }
        #pragma unroll
        for (int q = 0; q < 4; ++q) {
            int lin = tid + 256 * q;           // < 1024 float4s
            int rl = lin >> 4, c4 = lin & 15;
            *(float4*)(sh_adj + rl * TJ + c4 * 4) =
                *(const float4*)(adj + (size_t)(i0 + rl) * NN + jt + c4 * 4);
        }
        __syncthreads();

        // --- phase A: compute weights w(i,j), vectorized over j ---
        #pragma unroll
        for (int jb = 0; jb < TJ; jb += 32) {
            int j = jb + lane;
            float dv  = sh_dst[j];
            float Fv  = sh_F[j];
            float F5v = sh_F5[j];
            #pragma unroll
            for (int rp = 0; rp < 4; ++rp) {
                int r0 = 2 * rp, r1 = r0 + 1;
                float s0 = rs[r0] + dv;
                float c0 = (s0 > 0.f) ? rE[r0] * Fv : rE5[r0] * F5v;
                float w0 = c0 * sh_adj[(rbase + r0) * TJ + j];
                float s1 = rs[r1] + dv;
                float c1 = (s1 > 0.f) ? rE[r1] * Fv : rE5[r1] * F5v;
                float w1 = c1 * sh_adj[(rbase + r1) * TJ + j];
                ls[r0] += w0;
                ls[r1] += w1;
                sh_w[warp][j][rp] = make_float2(w0, w1);
            }
        }
        __syncwarp();

        // --- phase B: acc += w * h, b64-resident accumulators ---
        #pragma unroll 8
        for (int j = 0; j < TJ; ++j) {
            unsigned long long hb = dup_f32(sh_h[j * DH + lane]);  // conflict-free
            uint32_t wa = wbase + (uint32_t)j * 32u;
            unsigned long long w0, w1, w2, w3;
            asm("ld.shared.v2.b64 {%0,%1}, [%2];"    : "=l"(w0), "=l"(w1) : "r"(wa));
            asm("ld.shared.v2.b64 {%0,%1}, [%2+16];" : "=l"(w2), "=l"(w3) : "r"(wa));
            FFMA2(acc[0], w0, hb);
            FFMA2(acc[1], w1, hb);
            FFMA2(acc[2], w2, hb);
            FFMA2(acc[3], w3, hb);
        }
    }

    // --- epilogue: reduce row sums over lanes, normalize, write ---
    float rinv[8];
    #pragma unroll
    for (int r = 0; r < 8; ++r) {
        float v = ls[r];
        #pragma unroll
        for (int off = 16; off > 0; off >>= 1)
            v += __shfl_xor_sync(0xffffffffu, v, off);
        rinv[r] = 1.0f / v;
    }

    const int b = bh >> 2, hh = bh & 3;
    #pragma unroll
    for (int rp = 0; rp < 4; ++rp) {
        int r0 = 2 * rp;
        float a0, a1;
        unpack2(acc[rp], a0, a1);
        int i_a = i0 + rbase + r0;
        int i_b = i_a + 1;
        g_att[((size_t)b * NN + i_a) * DD + hh * DH + lane] = a0 * rinv[r0];
        g_att[((size_t)b * NN + i_b) * DD + hh * DH + lane] = a1 * rinv[r0 + 1];
    }
}

// ---------------- Kernel 4: out = att @ Wo^T + bo; y = x + out; LayerNorm ----
// grid 1024, block 128, 16 rows per block (same GEMM structure as k1).
__global__ __launch_bounds__(128) void k4_proj_ln(const float* __restrict__ x,
                                                  const float* __restrict__ Wo,
                                                  const float* __restrict__ bo,
                                                  const float* __restrict__ gamma,
                                                  const float* __restrict__ beta,
                                                  float* __restrict__ out) {
    __shared__ __align__(16) float sat[128][20];
    __shared__ float sW[32][129];
    __shared__ float sy[16][128];
    __shared__ float smu[16], srstd[16];

    const int t = threadIdx.x;
    const int row0 = blockIdx.x * 16;
    const float* ab = g_att + (size_t)row0 * DD;
    const uint32_t sat_addr = (uint32_t)__cvta_generic_to_shared(&sat[0][0]);

    #pragma unroll
    for (int m = 0; m < 16; ++m) sat[t][m] = ab[m * DD + t];

    unsigned long long acc[8];
    #pragma unroll
    for (int rp = 0; rp < 8; ++rp) acc[rp] = 0ull;

    for (int kt = 0; kt < DD; kt += 32) {
        __syncthreads();
        #pragma unroll
        for (int m = 0; m < 32; ++m) {
            int lin = t + 128 * m;
            int dp = lin >> 5, k = lin & 31;
            sW[k][dp] = Wo[dp * DD + kt + k];
        }
        __syncthreads();
        #pragma unroll
        for (int k = 0; k < 32; ++k) {
            unsigned long long wb = dup_f32(sW[k][t]);
            uint32_t ra = sat_addr + (uint32_t)(kt + k) * 80u;
            unsigned long long x0, x1, x2, x3, x4, x5, x6, x7;
            asm("ld.shared.v2.b64 {%0,%1}, [%2];"    : "=l"(x0), "=l"(x1) : "r"(ra));
            asm("ld.shared.v2.b64 {%0,%1}, [%2+16];" : "=l"(x2), "=l"(x3) : "r"(ra));
            asm("ld.shared.v2.b64 {%0,%1}, [%2+32];" : "=l"(x4), "=l"(x5) : "r"(ra));
            asm("ld.shared.v2.b64 {%0,%1}, [%2+48];" : "=l"(x6), "=l"(x7) : "r"(ra));
            FFMA2(acc[0], x0, wb);
            FFMA2(acc[1], x1, wb);
            FFMA2(acc[2], x2, wb);
            FFMA2(acc[3], x3, wb);
            FFMA2(acc[4], x4, wb);
            FFMA2(acc[5], x5, wb);
            FFMA2(acc[6], x6, wb);
            FFMA2(acc[7], x7, wb);
        }
    }
    __syncthreads();

    // y = x + o + bo, stash to smem + regs
    const float bov = bo[t];
    float yv[16];
    #pragma unroll
    for (int rp = 0; rp < 8; ++rp) {
        int r0 = 2 * rp;
        float a0, a1;
        unpack2(acc[rp], a0, a1);
        float y0 = x[(size_t)(row0 + r0) * DD + t]     + a0 + bov;
        float y1 = x[(size_t)(row0 + r0 + 1) * DD + t] + a1 + bov;
        yv[r0] = y0; yv[r0 + 1] = y1;
        sy[r0][t] = y0; sy[r0 + 1][t] = y1;
    }
    __syncthreads();

    // per-row mean/var: warp w handles rows 4w..4w+3
    {
        int w = t >> 5, lane = t & 31;
        #pragma unroll
        for (int rr = 0; rr < 4; ++rr) {
            int r = w * 4 + rr;
            float s = 0.f, q = 0.f;
            #pragma unroll
            for (int c = 0; c < 4; ++c) {
                float v = sy[r][lane + 32 * c];
                s += v;
                q += v * v;
            }
            #pragma unroll
            for (int off = 16; off > 0; off >>= 1) {
                s += __shfl_xor_sync(0xffffffffu, s, off);
                q += __shfl_xor_sync(0xffffffffu, q, off);
            }
            if (lane == 0) {
                float mu = s * (1.0f / DD);
                float var = q * (1.0f / DD) - mu * mu;
                smu[r] = mu;
                srstd[r] = rsqrtf(var + 1e-5f);
            }
        }
    }
    __syncthreads();

    const float gv = gamma[t], bev = beta[t];
    #pragma unroll
    for (int r = 0; r < 16; ++r) {
        out[(size_t)(row0 + r) * DD + t] = (yv[r] - smu[r]) * srstd[r] * gv + bev;
    }
}

// ---------------- launch ----------------
extern "C" void kernel_launch(void* const* d_in, const int* in_sizes, int n_in,
                              void* d_out, int out_size) {
    const float* x     = (const float*)d_in[0];
    const float* adj   = (const float*)d_in[1];
    const float* W     = (const float*)d_in[2];
    const float* a_src = (const float*)d_in[3];
    const float* a_dst = (const float*)d_in[4];
    const float* Wo    = (const float*)d_in[5];
    const float* bo    = (const float*)d_in[6];
    const float* gamma = (const float*)d_in[7];
    const float* beta  = (const float*)d_in[8];
    float* out = (float*)d_out;

    k1_proj<<<BN / 16, 128>>>(x, W);
    k2_srcdst<<<(NBH * NN) / 256, 256>>>(a_src, a_dst);
    k3_attn<<<dim3(NN / 64, NBH), 256>>>(adj);
    k4_proj_ln<<<BN / 16, 128>>>(x, Wo, bo, gamma, beta, out);
}

// round 7
// speedup vs baseline: 1.2996x; 1.2996x over previous
#include <cuda_runtime.h>
#include <cstdint>

// Problem constants
#define BB 8
#define NN 2048
#define DD 128
#define HH 4
#define DH 32
#define NBH 32          // B*H
#define BN 16384        // B*N

// ---------------- device scratch ----------------
__device__ float g_h[NBH * NN * DH];          // (b,h,n,dh) = 2M floats
__device__ float g_src[NBH * NN];
__device__ float g_dst[NBH * NN];
__device__ float g_E [NBH * NN];              // exp(src)
__device__ float g_E5[NBH * NN];              // exp(0.2*src)
__device__ float g_F [NBH * NN];              // exp(dst)
__device__ float g_F5[NBH * NN];              // exp(0.2*dst)
__device__ float g_att[BN * DD];              // attention output, (b,n,d)

// packed f32x2 helpers: accumulator stays resident as b64
#define FFMA2(accum, a64, b64) \
    asm("fma.rn.f32x2 %0, %1, %2, %0;" : "+l"(accum) : "l"(a64), "l"(b64))

__device__ __forceinline__ unsigned long long dup_f32(float v) {
    unsigned long long r;
    asm("mov.b64 %0, {%1, %1};" : "=l"(r) : "f"(v));
    return r;
}
__device__ __forceinline__ void unpack2(unsigned long long p, float &lo, float &hi) {
    asm("mov.b64 {%0, %1}, %2;" : "=f"(lo), "=f"(hi) : "l"(p));
}
__device__ __forceinline__ void cp16(uint32_t s, const void* g) {
    asm volatile("cp.async.cg.shared.global [%0], [%1], 16;" :: "r"(s), "l"(g));
}

// ---------------- Kernel 1: h = x @ W^T, stored (b,h,n,dh) ----------------
__global__ __launch_bounds__(128) void k1_proj(const float* __restrict__ x,
                                               const float* __restrict__ W) {
    __shared__ __align__(16) float sxt[128][20];   // [k][row], 80B rows (16B aligned)
    __shared__ float sW[32][129];                  // [k][d'], padded

    const int t = threadIdx.x;
    const int row0 = blockIdx.x * 16;
    const float* xb = x + (size_t)row0 * DD;
    const uint32_t sxt_addr = (uint32_t)__cvta_generic_to_shared(&sxt[0][0]);

    #pragma unroll
    for (int m = 0; m < 16; ++m) sxt[t][m] = xb[m * DD + t];   // coalesced

    unsigned long long acc[8];
    #pragma unroll
    for (int rp = 0; rp < 8; ++rp) acc[rp] = 0ull;

    for (int kt = 0; kt < DD; kt += 32) {
        __syncthreads();
        #pragma unroll
        for (int m = 0; m < 32; ++m) {
            int lin = t + 128 * m;
            int dp = lin >> 5, k = lin & 31;
            sW[k][dp] = W[dp * DD + kt + k];
        }
        __syncthreads();
        #pragma unroll
        for (int k = 0; k < 32; ++k) {
            unsigned long long wb = dup_f32(sW[k][t]);
            uint32_t ra = sxt_addr + (uint32_t)(kt + k) * 80u;
            unsigned long long x0, x1, x2, x3, x4, x5, x6, x7;
            asm("ld.shared.v2.b64 {%0,%1}, [%2];"    : "=l"(x0), "=l"(x1) : "r"(ra));
            asm("ld.shared.v2.b64 {%0,%1}, [%2+16];" : "=l"(x2), "=l"(x3) : "r"(ra));
            asm("ld.shared.v2.b64 {%0,%1}, [%2+32];" : "=l"(x4), "=l"(x5) : "r"(ra));
            asm("ld.shared.v2.b64 {%0,%1}, [%2+48];" : "=l"(x6), "=l"(x7) : "r"(ra));
            FFMA2(acc[0], x0, wb);
            FFMA2(acc[1], x1, wb);
            FFMA2(acc[2], x2, wb);
            FFMA2(acc[3], x3, wb);
            FFMA2(acc[4], x4, wb);
            FFMA2(acc[5], x5, wb);
            FFMA2(acc[6], x6, wb);
            FFMA2(acc[7], x7, wb);
        }
    }

    const int hh = t >> 5, dh = t & 31;
    #pragma unroll
    for (int rp = 0; rp < 8; ++rp) {
        float a0, a1;
        unpack2(acc[rp], a0, a1);
        int bn = row0 + 2 * rp;
        int b = bn >> 11, n = bn & 2047;
        size_t base = (((size_t)b * HH + hh) * NN + n) * DH + dh;
        g_h[base]      = a0;
        g_h[base + DH] = a1;
    }
}

// ---------------- Kernel 2: src/dst dots + exps ----------------
__global__ __launch_bounds__(256) void k2_srcdst(const float* __restrict__ a_src,
                                                 const float* __restrict__ a_dst) {
    int idx = blockIdx.x * 256 + threadIdx.x;   // = bh*N + n, < 65536
    int hh = (idx >> 11) & 3;
    const float* hrow = g_h + (size_t)idx * DH;
    const float* as = a_src + hh * DH;
    const float* ad = a_dst + hh * DH;
    float s = 0.f, d = 0.f;
    #pragma unroll
    for (int k = 0; k < DH; ++k) {
        float hv = hrow[k];
        s += hv * as[k];
        d += hv * ad[k];
    }
    g_src[idx] = s;
    g_dst[idx] = d;
    g_E [idx] = __expf(s);
    g_E5[idx] = __expf(0.2f * s);
    g_F [idx] = __expf(d);
    g_F5[idx] = __expf(0.2f * d);
}

// ---------------- Kernel 3: fused attention, cp.async double-buffered ------
// grid (N/64, B*H), block 256 (8 warps). Warp w owns rows i0+8w..i0+8w+7.
// j-tiles of 32, 2-stage cp.async pipeline hides all global latency.
#define TJ 32
__global__ __launch_bounds__(256) void k3_attn(const float* __restrict__ adj) {
    __shared__ __align__(16) float  sh_h  [2][TJ * DH];    // 8 KB
    __shared__ __align__(16) float  sh_adj[2][64 * TJ];    // 16 KB
    __shared__ __align__(16) float  sh_sc [2][3][TJ];      // 768 B
    __shared__ __align__(16) float2 sh_w  [8][TJ][4];      // 8 KB

    const int bh = blockIdx.y;
    const int i0 = blockIdx.x * 64;
    const int tid = threadIdx.x;
    const int warp = tid >> 5, lane = tid & 31;
    const int rbase = warp * 8;

    const float* hbh = g_h + (size_t)bh * NN * DH;
    const int jo = bh * NN;

    const uint32_t h_addr   = (uint32_t)__cvta_generic_to_shared(&sh_h[0][0]);
    const uint32_t adj_addr = (uint32_t)__cvta_generic_to_shared(&sh_adj[0][0]);
    const uint32_t sc_addr  = (uint32_t)__cvta_generic_to_shared(&sh_sc[0][0][0]);
    const uint32_t wbase    = (uint32_t)__cvta_generic_to_shared(&sh_w[warp][0][0]);

    // per-row constants (uniform per warp)
    float rs[8], rE[8], rE5[8];
    {
        int gb = bh * NN + i0 + rbase;
        #pragma unroll
        for (int r = 0; r < 8; ++r) {
            rs[r]  = g_src[gb + r];
            rE[r]  = g_E [gb + r];
            rE5[r] = g_E5[gb + r];
        }
    }

    unsigned long long acc[4];
    #pragma unroll
    for (int rp = 0; rp < 4; ++rp) acc[rp] = 0ull;
    float ls[8];
    #pragma unroll
    for (int r = 0; r < 8; ++r) ls[r] = 0.f;

    // ---- staging lambda: fully async, no register round-trip ----
    auto stage = [&](int b, int jt) {
        // h tile: 32 rows x 32 dh = 256 float4, 1 per thread (contiguous)
        cp16(h_addr + (uint32_t)(b * (TJ * DH * 4)) + (uint32_t)tid * 16u,
             hbh + (size_t)jt * DH + tid * 4);
        // adj tile: 64 rows x 32 cols = 512 float4, 2 per thread
        #pragma unroll
        for (int q = 0; q < 2; ++q) {
            int lin = tid + 256 * q;           // 0..511
            int rl = lin >> 3, c4 = lin & 7;   // 8 float4 per row
            cp16(adj_addr + (uint32_t)(b * (64 * TJ * 4)) + (uint32_t)((rl * TJ + c4 * 4) * 4),
                 adj + (size_t)(i0 + rl) * NN + jt + c4 * 4);
        }
        // dst/F/F5: 8 float4 each
        if (tid < 24) {
            int arr = tid >> 3, idx = tid & 7;
            const float* src = (arr == 0 ? g_dst : (arr == 1 ? g_F : g_F5)) + jo + jt + idx * 4;
            cp16(sc_addr + (uint32_t)(b * (3 * TJ * 4)) + (uint32_t)(arr * (TJ * 4) + idx * 16), src);
        }
    };

    // prologue: prefetch tile 0
    stage(0, 0);
    asm volatile("cp.async.commit_group;");

    for (int jt = 0, it = 0; jt < NN; jt += TJ, ++it) {
        const int cb = it & 1;
        // prefetch next tile into the other buffer (freed by last iter's barrier)
        if (jt + TJ < NN) stage(cb ^ 1, jt + TJ);
        asm volatile("cp.async.commit_group;");
        asm volatile("cp.async.wait_group 1;");   // current tile's group done
        __syncthreads();

        // --- phase A: weights for j = lane ---
        {
            const float dv  = sh_sc[cb][0][lane];
            const float Fv  = sh_sc[cb][1][lane];
            const float F5v = sh_sc[cb][2][lane];
            #pragma unroll
            for (int rp = 0; rp < 4; ++rp) {
                int r0 = 2 * rp, r1 = r0 + 1;
                float s0 = rs[r0] + dv;
                float c0 = (s0 > 0.f) ? rE[r0] * Fv : rE5[r0] * F5v;
                float w0 = c0 * sh_adj[cb][(rbase + r0) * TJ + lane];
                float s1 = rs[r1] + dv;
                float c1 = (s1 > 0.f) ? rE[r1] * Fv : rE5[r1] * F5v;
                float w1 = c1 * sh_adj[cb][(rbase + r1) * TJ + lane];
                ls[r0] += w0;
                ls[r1] += w1;
                sh_w[warp][lane][rp] = make_float2(w0, w1);
            }
        }
        __syncwarp();

        // --- phase B: acc += w * h ---
        #pragma unroll 8
        for (int j = 0; j < TJ; ++j) {
            unsigned long long hb = dup_f32(sh_h[cb][j * DH + lane]);  // conflict-free
            uint32_t wa = wbase + (uint32_t)j * 32u;
            unsigned long long w0, w1, w2, w3;
            asm("ld.shared.v2.b64 {%0,%1}, [%2];"    : "=l"(w0), "=l"(w1) : "r"(wa));
            asm("ld.shared.v2.b64 {%0,%1}, [%2+16];" : "=l"(w2), "=l"(w3) : "r"(wa));
            FFMA2(acc[0], w0, hb);
            FFMA2(acc[1], w1, hb);
            FFMA2(acc[2], w2, hb);
            FFMA2(acc[3], w3, hb);
        }
        __syncthreads();   // buffer cb free for prefetch next iter
    }

    // --- epilogue: reduce row sums over lanes, normalize, write ---
    float rinv[8];
    #pragma unroll
    for (int r = 0; r < 8; ++r) {
        float v = ls[r];
        #pragma unroll
        for (int off = 16; off > 0; off >>= 1)
            v += __shfl_xor_sync(0xffffffffu, v, off);
        rinv[r] = 1.0f / v;
    }

    const int b = bh >> 2, hh = bh & 3;
    #pragma unroll
    for (int rp = 0; rp < 4; ++rp) {
        int r0 = 2 * rp;
        float a0, a1;
        unpack2(acc[rp], a0, a1);
        int i_a = i0 + rbase + r0;
        int i_b = i_a + 1;
        g_att[((size_t)b * NN + i_a) * DD + hh * DH + lane] = a0 * rinv[r0];
        g_att[((size_t)b * NN + i_b) * DD + hh * DH + lane] = a1 * rinv[r0 + 1];
    }
}
#undef TJ

// ---------------- Kernel 4: out = att @ Wo^T + bo; y = x + out; LayerNorm ----
__global__ __launch_bounds__(128) void k4_proj_ln(const float* __restrict__ x,
                                                  const float* __restrict__ Wo,
                                                  const float* __restrict__ bo,
                                                  const float* __restrict__ gamma,
                                                  const float* __restrict__ beta,
                                                  float* __restrict__ out) {
    __shared__ __align__(16) float sat[128][20];
    __shared__ float sW[32][129];
    __shared__ float sy[16][128];
    __shared__ float smu[16], srstd[16];

    const int t = threadIdx.x;
    const int row0 = blockIdx.x * 16;
    const float* ab = g_att + (size_t)row0 * DD;
    const uint32_t sat_addr = (uint32_t)__cvta_generic_to_shared(&sat[0][0]);

    #pragma unroll
    for (int m = 0; m < 16; ++m) sat[t][m] = ab[m * DD + t];

    unsigned long long acc[8];
    #pragma unroll
    for (int rp = 0; rp < 8; ++rp) acc[rp] = 0ull;

    for (int kt = 0; kt < DD; kt += 32) {
        __syncthreads();
        #pragma unroll
        for (int m = 0; m < 32; ++m) {
            int lin = t + 128 * m;
            int dp = lin >> 5, k = lin & 31;
            sW[k][dp] = Wo[dp * DD + kt + k];
        }
        __syncthreads();
        #pragma unroll
        for (int k = 0; k < 32; ++k) {
            unsigned long long wb = dup_f32(sW[k][t]);
            uint32_t ra = sat_addr + (uint32_t)(kt + k) * 80u;
            unsigned long long x0, x1, x2, x3, x4, x5, x6, x7;
            asm("ld.shared.v2.b64 {%0,%1}, [%2];"    : "=l"(x0), "=l"(x1) : "r"(ra));
            asm("ld.shared.v2.b64 {%0,%1}, [%2+16];" : "=l"(x2), "=l"(x3) : "r"(ra));
            asm("ld.shared.v2.b64 {%0,%1}, [%2+32];" : "=l"(x4), "=l"(x5) : "r"(ra));
            asm("ld.shared.v2.b64 {%0,%1}, [%2+48];" : "=l"(x6), "=l"(x7) : "r"(ra));
            FFMA2(acc[0], x0, wb);
            FFMA2(acc[1], x1, wb);
            FFMA2(acc[2], x2, wb);
            FFMA2(acc[3], x3, wb);
            FFMA2(acc[4], x4, wb);
            FFMA2(acc[5], x5, wb);
            FFMA2(acc[6], x6, wb);
            FFMA2(acc[7], x7, wb);
        }
    }
    __syncthreads();

    const float bov = bo[t];
    float yv[16];
    #pragma unroll
    for (int rp = 0; rp < 8; ++rp) {
        int r0 = 2 * rp;
        float a0, a1;
        unpack2(acc[rp], a0, a1);
        float y0 = x[(size_t)(row0 + r0) * DD + t]     + a0 + bov;
        float y1 = x[(size_t)(row0 + r0 + 1) * DD + t] + a1 + bov;
        yv[r0] = y0; yv[r0 + 1] = y1;
        sy[r0][t] = y0; sy[r0 + 1][t] = y1;
    }
    __syncthreads();

    {
        int w = t >> 5, lane = t & 31;
        #pragma unroll
        for (int rr = 0; rr < 4; ++rr) {
            int r = w * 4 + rr;
            float s = 0.f, q = 0.f;
            #pragma unroll
            for (int c = 0; c < 4; ++c) {
                float v = sy[r][lane + 32 * c];
                s += v;
                q += v * v;
            }
            #pragma unroll
            for (int off = 16; off > 0; off >>= 1) {
                s += __shfl_xor_sync(0xffffffffu, s, off);
                q += __shfl_xor_sync(0xffffffffu, q, off);
            }
            if (lane == 0) {
                float mu = s * (1.0f / DD);
                float var = q * (1.0f / DD) - mu * mu;
                smu[r] = mu;
                srstd[r] = rsqrtf(var + 1e-5f);
            }
        }
    }
    __syncthreads();

    const float gv = gamma[t], bev = beta[t];
    #pragma unroll
    for (int r = 0; r < 16; ++r) {
        out[(size_t)(row0 + r) * DD + t] = (yv[r] - smu[r]) * srstd[r] * gv + bev;
    }
}

// ---------------- launch ----------------
extern "C" void kernel_launch(void* const* d_in, const int* in_sizes, int n_in,
                              void* d_out, int out_size) {
    const float* x     = (const float*)d_in[0];
    const float* adj   = (const float*)d_in[1];
    const float* W     = (const float*)d_in[2];
    const float* a_src = (const float*)d_in[3];
    const float* a_dst = (const float*)d_in[4];
    const float* Wo    = (const float*)d_in[5];
    const float* bo    = (const float*)d_in[6];
    const float* gamma = (const float*)d_in[7];
    const float* beta  = (const float*)d_in[8];
    float* out = (float*)d_out;

    k1_proj<<<BN / 16, 128>>>(x, W);
    k2_srcdst<<<(NBH * NN) / 256, 256>>>(a_src, a_dst);
    k3_attn<<<dim3(NN / 64, NBH), 256>>>(adj);
    k4_proj_ln<<<BN / 16, 128>>>(x, Wo, bo, gamma, beta, out);
}

// round 10
// speedup vs baseline: 1.5326x; 1.1793x over previous
#include <cuda_runtime.h>
#include <cstdint>

// Problem constants
#define BB 8
#define NN 2048
#define DD 128
#define HH 4
#define DH 32
#define NBH 32          // B*H
#define BN 16384        // B*N

// k3 tensor tiling
#define MT 128          // i rows per CTA
#define KT 64           // j per K-tile
#define NTILES 32       // NN / KT
#define NBP 48          // padded B rows: 32 dh + 1 ones + 15 zero
#define BSPLIT_BYTES (NBP * 128)      // 6144
#define BTILE_BYTES  (2 * BSPLIT_BYTES) // 12288 (hi + lo)

// ---------------- device scratch ----------------
__device__ float g_h[NBH * NN * DH];          // (b,h,n,dh)
__device__ float g_src[NBH * NN];
__device__ float g_dst[NBH * NN];
__device__ float g_E [NBH * NN];              // exp(src)
__device__ float g_E5[NBH * NN];              // exp(0.2*src)
__device__ float g_F [NBH * NN];              // exp(dst)
__device__ float g_F5[NBH * NN];              // exp(0.2*dst)
__device__ float g_att[BN * DD];              // attention output, (b,n,d)
__device__ __align__(16) unsigned char g_B[NBH * NTILES * BTILE_BYTES]; // ~12.6MB bf16 hi/lo B tiles

// packed f32x2 helpers (k1/k4)
#define FFMA2(accum, a64, b64) \
    asm("fma.rn.f32x2 %0, %1, %2, %0;" : "+l"(accum) : "l"(a64), "l"(b64))

__device__ __forceinline__ unsigned long long dup_f32(float v) {
    unsigned long long r;
    asm("mov.b64 %0, {%1, %1};" : "=l"(r) : "f"(v));
    return r;
}
__device__ __forceinline__ void unpack2(unsigned long long p, float &lo, float &hi) {
    asm("mov.b64 {%0, %1}, %2;" : "=f"(lo), "=f"(hi) : "l"(p));
}
__device__ __forceinline__ void cp16(uint32_t s, const void* g) {
    asm volatile("cp.async.cg.shared.global [%0], [%1], 16;" :: "r"(s), "l"(g));
}
__device__ __forceinline__ uint32_t pack_bf16x2(float lo, float hi) {
    uint32_t r;
    asm("cvt.rn.bf16x2.f32 %0, %1, %2;" : "=r"(r) : "f"(hi), "f"(lo));
    return r;
}
__device__ __forceinline__ void ldsm4(uint32_t* r, uint32_t addr) {
    asm volatile("ldmatrix.sync.aligned.m8n8.x4.shared.b16 {%0,%1,%2,%3}, [%4];"
                 : "=r"(r[0]), "=r"(r[1]), "=r"(r[2]), "=r"(r[3]) : "r"(addr));
}
__device__ __forceinline__ void mma_bf16(float* c, const uint32_t* a,
                                         uint32_t b0, uint32_t b1) {
    asm volatile("mma.sync.aligned.m16n8k16.row.col.f32.bf16.bf16.f32 "
                 "{%0,%1,%2,%3}, {%4,%5,%6,%7}, {%8,%9}, {%0,%1,%2,%3};"
                 : "+f"(c[0]), "+f"(c[1]), "+f"(c[2]), "+f"(c[3])
                 : "r"(a[0]), "r"(a[1]), "r"(a[2]), "r"(a[3]), "r"(b0), "r"(b1));
}

// ---------------- Kernel 1: h = x @ W^T, stored (b,h,n,dh) ----------------
__global__ __launch_bounds__(128) void k1_proj(const float* __restrict__ x,
                                               const float* __restrict__ W) {
    __shared__ __align__(16) float sxt[128][20];
    __shared__ float sW[32][129];

    const int t = threadIdx.x;
    const int row0 = blockIdx.x * 16;
    const float* xb = x + (size_t)row0 * DD;
    const uint32_t sxt_addr = (uint32_t)__cvta_generic_to_shared(&sxt[0][0]);

    #pragma unroll
    for (int m = 0; m < 16; ++m) sxt[t][m] = xb[m * DD + t];

    unsigned long long acc[8];
    #pragma unroll
    for (int rp = 0; rp < 8; ++rp) acc[rp] = 0ull;

    for (int kt = 0; kt < DD; kt += 32) {
        __syncthreads();
        #pragma unroll
        for (int m = 0; m < 32; ++m) {
            int lin = t + 128 * m;
            int dp = lin >> 5, k = lin & 31;
            sW[k][dp] = W[dp * DD + kt + k];
        }
        __syncthreads();
        #pragma unroll
        for (int k = 0; k < 32; ++k) {
            unsigned long long wb = dup_f32(sW[k][t]);
            uint32_t ra = sxt_addr + (uint32_t)(kt + k) * 80u;
            unsigned long long x0, x1, x2, x3, x4, x5, x6, x7;
            asm("ld.shared.v2.b64 {%0,%1}, [%2];"    : "=l"(x0), "=l"(x1) : "r"(ra));
            asm("ld.shared.v2.b64 {%0,%1}, [%2+16];" : "=l"(x2), "=l"(x3) : "r"(ra));
            asm("ld.shared.v2.b64 {%0,%1}, [%2+32];" : "=l"(x4), "=l"(x5) : "r"(ra));
            asm("ld.shared.v2.b64 {%0,%1}, [%2+48];" : "=l"(x6), "=l"(x7) : "r"(ra));
            FFMA2(acc[0], x0, wb);
            FFMA2(acc[1], x1, wb);
            FFMA2(acc[2], x2, wb);
            FFMA2(acc[3], x3, wb);
            FFMA2(acc[4], x4, wb);
            FFMA2(acc[5], x5, wb);
            FFMA2(acc[6], x6, wb);
            FFMA2(acc[7], x7, wb);
        }
    }

    const int hh = t >> 5, dh = t & 31;
    #pragma unroll
    for (int rp = 0; rp < 8; ++rp) {
        float a0, a1;
        unpack2(acc[rp], a0, a1);
        int bn = row0 + 2 * rp;
        int b = bn >> 11, n = bn & 2047;
        size_t base = (((size_t)b * HH + hh) * NN + n) * DH + dh;
        g_h[base]      = a0;
        g_h[base + DH] = a1;
    }
}

// ---------------- Kernel 2: src/dst dots + exps ----------------
__global__ __launch_bounds__(256) void k2_srcdst(const float* __restrict__ a_src,
                                                 const float* __restrict__ a_dst) {
    int idx = blockIdx.x * 256 + threadIdx.x;
    int hh = (idx >> 11) & 3;
    const float* hrow = g_h + (size_t)idx * DH;
    const float* as = a_src + hh * DH;
    const float* ad = a_dst + hh * DH;
    float s = 0.f, d = 0.f;
    #pragma unroll
    for (int k = 0; k < DH; ++k) {
        float hv = hrow[k];
        s += hv * as[k];
        d += hv * ad[k];
    }
    g_src[idx] = s;
    g_dst[idx] = d;
    g_E [idx] = __expf(s);
    g_E5[idx] = __expf(0.2f * s);
    g_F [idx] = __expf(d);
    g_F5[idx] = __expf(0.2f * d);
}

// ---------------- Kernel 2b: build swizzled bf16 hi/lo B tiles ----------------
// B tile per (bh, jt): [NBP=48 rows][KT=64 cols] bf16, 128B rows, XOR-swizzled.
// rows 0..31: hT (B[n][k] = h[jt+k][n]); row 32: ones(hi)/zeros(lo); rows 33..47: 0.
__global__ __launch_bounds__(128) void k2b_btiles() {
    __shared__ float sh[64][33];
    const int bh = blockIdx.y, t = blockIdx.x, tid = threadIdx.x;
    const float* hsrc = g_h + ((size_t)bh * NN + t * KT) * DH;

    #pragma unroll
    for (int i = 0; i < 4; ++i) {
        int c = tid + 128 * i;                   // 0..511 float4s
        float4 v = ((const float4*)hsrc)[c];
        int k = c >> 3, n4 = c & 7;
        sh[k][n4 * 4 + 0] = v.x;
        sh[k][n4 * 4 + 1] = v.y;
        sh[k][n4 * 4 + 2] = v.z;
        sh[k][n4 * 4 + 3] = v.w;
    }
    __syncthreads();

    unsigned char* outhi = g_B + (size_t)(bh * NTILES + t) * BTILE_BYTES;
    unsigned char* outlo = outhi + BSPLIT_BYTES;

    #pragma unroll
    for (int i = 0; i < 3; ++i) {
        int ch = tid + 128 * i;                  // 16B chunk id, 0..383
        int n = ch >> 3, c8 = ch & 7;
        uint32_t hiw[4], low[4];
        #pragma unroll
        for (int q = 0; q < 4; ++q) {
            float v0, v1;
            if (n < 32)      { v0 = sh[c8 * 8 + 2 * q][n]; v1 = sh[c8 * 8 + 2 * q + 1][n]; }
            else if (n == 32){ v0 = 1.f; v1 = 1.f; }
            else             { v0 = 0.f; v1 = 0.f; }
            uint32_t hw = pack_bf16x2(v0, v1);
            float f0 = __uint_as_float(hw << 16);
            float f1 = __uint_as_float(hw & 0xffff0000u);
            hiw[q] = hw;
            low[q] = (n <= 32) ? pack_bf16x2(v0 - f0, v1 - f1) : 0u;
        }
        uint32_t off = (uint32_t)(n * 128 + (c8 * 16 ^ ((n & 7) << 4)));
        *(uint4*)(outhi + off) = make_uint4(hiw[0], hiw[1], hiw[2], hiw[3]);
        *(uint4*)(outlo + off) = make_uint4(low[0], low[1], low[2], low[3]);
    }
}

// ---------------- Kernel 3: warp-MMA attention ----------------
// grid (16 i-blocks, 32 bh), block 256 (8 warps x 16 rows).
// Per 64-j tile: gen w (bf16 hi/lo, swizzled smem) -> compensated bf16 MMAs
// (hi*Bhi + lo*Bhi + hi*Blo). D[128 x 40]: cols 0-31 out, col 32 = row sum.
__global__ __launch_bounds__(256) void k3_attn_tc(const float* __restrict__ adj) {
    __shared__ __align__(128) unsigned char sB[BTILE_BYTES];     // 12 KB
    __shared__ __align__(128) unsigned char sWhi[MT * 128];      // 16 KB
    __shared__ __align__(128) unsigned char sWlo[MT * 128];      // 16 KB
    __shared__ float sh_rs[MT], sh_rE[MT], sh_rE5[MT];

    const int bh = blockIdx.y;
    const int i0 = blockIdx.x * MT;
    const int tid = threadIdx.x;
    const int warp = tid >> 5, lane = tid & 31;

    if (tid < MT) {
        int gi = bh * NN + i0 + tid;
        sh_rs [tid] = g_src[gi];
        sh_rE [tid] = g_E [gi];
        sh_rE5[tid] = g_E5[gi];
    }
    __syncthreads();

    const uint32_t sB_a   = (uint32_t)__cvta_generic_to_shared(sB);
    const uint32_t sWhi_a = (uint32_t)__cvta_generic_to_shared(sWhi);
    const uint32_t sWlo_a = (uint32_t)__cvta_generic_to_shared(sWlo);

    const int g0 = warp * 16;                 // this warp's 16 i-rows
    const int lr = lane & 7, lq = lane >> 3;
    const uint32_t xr = (uint32_t)lr << 4;    // swizzle term (row&7)<<4

    // ldmatrix address components (per lane, loop-invariant)
    const uint32_t a_rowoff = (uint32_t)(g0 + lr + ((lq & 1) << 3)) * 128u;
    const uint32_t a_cbx = (uint32_t)(lq >> 1) << 4;
    const uint32_t b_rowadd = (uint32_t)(lr + ((lq >> 1) << 3));
    const uint32_t b_cbx = (uint32_t)(lq & 1) << 4;

    float c[5][4];
    #pragma unroll
    for (int nt = 0; nt < 5; ++nt)
        #pragma unroll
        for (int q = 0; q < 4; ++q) c[nt][q] = 0.f;

    const int jo = bh * NN;
    const int m0 = g0;

    for (int t = 0; t < NTILES; ++t) {
        const int jt = t * KT;

        // --- stage B tile (pre-swizzled blob) via cp.async, overlap with gen ---
        {
            const unsigned char* gBt = g_B + (size_t)(bh * NTILES + t) * BTILE_BYTES;
            #pragma unroll
            for (int i = 0; i < 3; ++i) {
                int idx = tid + 256 * i;         // 16B chunks, 768 total
                cp16(sB_a + (uint32_t)idx * 16u, gBt + idx * 16);
            }
            asm volatile("cp.async.commit_group;");
        }

        // --- gen phase: w(i,j) -> bf16 hi/lo into swizzled A tiles ---
        {
            const int jg = jo + jt + 2 * lane;
            const float2 dv  = *(const float2*)&g_dst[jg];
            const float2 Fv  = *(const float2*)&g_F [jg];
            const float2 F5v = *(const float2*)&g_F5[jg];
            const float* arow = adj + (size_t)(i0 + m0) * NN + jt + 2 * lane;

            #pragma unroll
            for (int r = 0; r < 16; ++r) {
                const int m = m0 + r;
                const float rs_m  = sh_rs[m];
                const float rE_m  = sh_rE[m];
                const float rE5_m = sh_rE5[m];
                const float2 av = *(const float2*)(arow + (size_t)r * NN);

                float s0 = rs_m + dv.x;
                float c0 = (s0 > 0.f) ? rE_m * Fv.x : rE5_m * F5v.x;
                float w0 = c0 * av.x;
                float s1 = rs_m + dv.y;
                float c1 = (s1 > 0.f) ? rE_m * Fv.y : rE5_m * F5v.y;
                float w1 = c1 * av.y;

                uint32_t hw = pack_bf16x2(w0, w1);
                float f0 = __uint_as_float(hw << 16);
                float f1 = __uint_as_float(hw & 0xffff0000u);
                uint32_t lw = pack_bf16x2(w0 - f0, w1 - f1);

                uint32_t off = (uint32_t)(m * 128 + ((lane * 4) ^ ((m & 7) << 4)));
                asm volatile("st.shared.b32 [%0], %1;" :: "r"(sWhi_a + off), "r"(hw) : "memory");
                asm volatile("st.shared.b32 [%0], %1;" :: "r"(sWlo_a + off), "r"(lw) : "memory");
            }
        }

        asm volatile("cp.async.wait_group 0;");
        __syncthreads();

        // --- MMA phase: 4 k16-chunks, 5 n8-tiles, 3 compensated products ---
        #pragma unroll
        for (int ch = 0; ch < 4; ++ch) {
            const uint32_t cba = (uint32_t)(ch * 32) + a_cbx;
            uint32_t ahi[4], alo[4];
            ldsm4(ahi, sWhi_a + a_rowoff + (cba ^ xr));
            ldsm4(alo, sWlo_a + a_rowoff + (cba ^ xr));
            const uint32_t cbb = (uint32_t)(ch * 32) + b_cbx;
            #pragma unroll
            for (int p = 0; p < 3; ++p) {
                const uint32_t baddr = sB_a + (uint32_t)(p * 16 + b_rowadd) * 128u + (cbb ^ xr);
                uint32_t bh4[4];
                ldsm4(bh4, baddr);
                mma_bf16(c[2 * p], ahi, bh4[0], bh4[1]);
                mma_bf16(c[2 * p], alo, bh4[0], bh4[1]);
                if (p < 2) {
                    mma_bf16(c[2 * p + 1], ahi, bh4[2], bh4[3]);
                    mma_bf16(c[2 * p + 1], alo, bh4[2], bh4[3]);
                }
                uint32_t bl4[4];
                ldsm4(bl4, baddr + BSPLIT_BYTES);
                mma_bf16(c[2 * p], ahi, bl4[0], bl4[1]);
                if (p < 2) mma_bf16(c[2 * p + 1], ahi, bl4[2], bl4[3]);
            }
        }
        __syncthreads();   // sB free for next tile's staging
    }

    // --- epilogue: row sums from col 32 (tile 4), normalize, store ---
    const float s_lo = __shfl_sync(0xffffffffu, c[4][0], lane & ~3);
    const float s_hi = __shfl_sync(0xffffffffu, c[4][2], lane & ~3);
    const float r0 = 1.0f / s_lo;
    const float r1 = 1.0f / s_hi;

    const int b = bh >> 2, hh = bh & 3;
    const int ia = i0 + g0 + (lane >> 2);
    float* dst0 = g_att + ((size_t)b * NN + ia) * DD + hh * DH + 2 * (lane & 3);
    float* dst1 = dst0 + 8 * (size_t)DD;   // row ia+8
    #pragma unroll
    for (int nt = 0; nt < 4; ++nt) {
        *(float2*)(dst0 + nt * 8) = make_float2(c[nt][0] * r0, c[nt][1] * r0);
        *(float2*)(dst1 + nt * 8) = make_float2(c[nt][2] * r1, c[nt][3] * r1);
    }
}

// ---------------- Kernel 4: out = att @ Wo^T + bo; y = x + out; LayerNorm ----
__global__ __launch_bounds__(128) void k4_proj_ln(const float* __restrict__ x,
                                                  const float* __restrict__ Wo,
                                                  const float* __restrict__ bo,
                                                  const float* __restrict__ gamma,
                                                  const float* __restrict__ beta,
                                                  float* __restrict__ out) {
    __shared__ __align__(16) float sat[128][20];
    __shared__ float sW[32][129];
    __shared__ float sy[16][128];
    __shared__ float smu[16], srstd[16];

    const int t = threadIdx.x;
    const int row0 = blockIdx.x * 16;
    const float* ab = g_att + (size_t)row0 * DD;
    const uint32_t sat_addr = (uint32_t)__cvta_generic_to_shared(&sat[0][0]);

    #pragma unroll
    for (int m = 0; m < 16; ++m) sat[t][m] = ab[m * DD + t];

    unsigned long long acc[8];
    #pragma unroll
    for (int rp = 0; rp < 8; ++rp) acc[rp] = 0ull;

    for (int kt = 0; kt < DD; kt += 32) {
        __syncthreads();
        #pragma unroll
        for (int m = 0; m < 32; ++m) {
            int lin = t + 128 * m;
            int dp = lin >> 5, k = lin & 31;
            sW[k][dp] = Wo[dp * DD + kt + k];
        }
        __syncthreads();
        #pragma unroll
        for (int k = 0; k < 32; ++k) {
            unsigned long long wb = dup_f32(sW[k][t]);
            uint32_t ra = sat_addr + (uint32_t)(kt + k) * 80u;
            unsigned long long x0, x1, x2, x3, x4, x5, x6, x7;
            asm("ld.shared.v2.b64 {%0,%1}, [%2];"    : "=l"(x0), "=l"(x1) : "r"(ra));
            asm("ld.shared.v2.b64 {%0,%1}, [%2+16];" : "=l"(x2), "=l"(x3) : "r"(ra));
            asm("ld.shared.v2.b64 {%0,%1}, [%2+32];" : "=l"(x4), "=l"(x5) : "r"(ra));
            asm("ld.shared.v2.b64 {%0,%1}, [%2+48];" : "=l"(x6), "=l"(x7) : "r"(ra));
            FFMA2(acc[0], x0, wb);
            FFMA2(acc[1], x1, wb);
            FFMA2(acc[2], x2, wb);
            FFMA2(acc[3], x3, wb);
            FFMA2(acc[4], x4, wb);
            FFMA2(acc[5], x5, wb);
            FFMA2(acc[6], x6, wb);
            FFMA2(acc[7], x7, wb);
        }
    }
    __syncthreads();

    const float bov = bo[t];
    float yv[16];
    #pragma unroll
    for (int rp = 0; rp < 8; ++rp) {
        int r0 = 2 * rp;
        float a0, a1;
        unpack2(acc[rp], a0, a1);
        float y0 = x[(size_t)(row0 + r0) * DD + t]     + a0 + bov;
        float y1 = x[(size_t)(row0 + r0 + 1) * DD + t] + a1 + bov;
        yv[r0] = y0; yv[r0 + 1] = y1;
        sy[r0][t] = y0; sy[r0 + 1][t] = y1;
    }
    __syncthreads();

    {
        int w = t >> 5, lane = t & 31;
        #pragma unroll
        for (int rr = 0; rr < 4; ++rr) {
            int r = w * 4 + rr;
            float s = 0.f, q = 0.f;
            #pragma unroll
            for (int cc = 0; cc < 4; ++cc) {
                float v = sy[r][lane + 32 * cc];
                s += v;
                q += v * v;
            }
            #pragma unroll
            for (int off = 16; off > 0; off >>= 1) {
                s += __shfl_xor_sync(0xffffffffu, s, off);
                q += __shfl_xor_sync(0xffffffffu, q, off);
            }
            if (lane == 0) {
                float mu = s * (1.0f / DD);
                float var = q * (1.0f / DD) - mu * mu;
                smu[r] = mu;
                srstd[r] = rsqrtf(var + 1e-5f);
            }
        }
    }
    __syncthreads();

    const float gv = gamma[t], bev = beta[t];
    #pragma unroll
    for (int r = 0; r < 16; ++r) {
        out[(size_t)(row0 + r) * DD + t] = (yv[r] - smu[r]) * srstd[r] * gv + bev;
    }
}

// ---------------- launch ----------------
extern "C" void kernel_launch(void* const* d_in, const int* in_sizes, int n_in,
                              void* d_out, int out_size) {
    const float* x     = (const float*)d_in[0];
    const float* adj   = (const float*)d_in[1];
    const float* W     = (const float*)d_in[2];
    const float* a_src = (const float*)d_in[3];
    const float* a_dst = (const float*)d_in[4];
    const float* Wo    = (const float*)d_in[5];
    const float* bo    = (const float*)d_in[6];
    const float* gamma = (const float*)d_in[7];
    const float* beta  = (const float*)d_in[8];
    float* out = (float*)d_out;

    k1_proj<<<BN / 16, 128>>>(x, W);
    k2_srcdst<<<(NBH * NN) / 256, 256>>>(a_src, a_dst);
    k2b_btiles<<<dim3(NTILES, NBH), 128>>>();
    k3_attn_tc<<<dim3(NN / MT, NBH), 256>>>(adj);
    k4_proj_ln<<<BN / 16, 128>>>(x, Wo, bo, gamma, beta, out);
}

// round 11
// speedup vs baseline: 2.5634x; 1.6726x over previous
#include <cuda_runtime.h>
#include <cstdint>

// Problem constants
#define BB 8
#define NN 2048
#define DD 128
#define HH 4
#define DH 32
#define NBH 32          // B*H
#define BN 16384        // B*N

// k3 tensor tiling
#define MT 128          // i rows per CTA
#define KT 64           // j per K-tile
#define NTILES 32       // NN / KT
#define NBP 40          // padded B rows: 32 dh + 1 ones + 7 zero
#define BSPLIT_BYTES (NBP * 128)        // 5120
#define BTILE_BYTES  (2 * BSPLIT_BYTES) // 10240 (hi + lo)

// dynamic smem layout for k3
#define SM_WHI   0u
#define SM_WLO   16384u
#define SM_SB    32768u                  // 2 x 10240
#define SM_RS    53248u
#define SM_RE    53760u
#define SM_RE5   54272u
#define SM_TOTAL 54784u

// ---------------- device scratch ----------------
__device__ float g_h[NBH * NN * DH];          // (b,h,n,dh)
__device__ float g_src[NBH * NN];
__device__ float g_dst[NBH * NN];
__device__ float g_E [NBH * NN];              // exp(src)
__device__ float g_E5[NBH * NN];              // exp(0.2*src)
__device__ float g_F [NBH * NN];              // exp(dst)
__device__ float g_F5[NBH * NN];              // exp(0.2*dst)
__device__ float g_att[BN * DD];              // attention output, (b,n,d)
__device__ __align__(16) unsigned char g_B[NBH * NTILES * BTILE_BYTES]; // ~10.5MB bf16 hi/lo B tiles

// packed f32x2 helpers (k1/k4)
#define FFMA2(accum, a64, b64) \
    asm("fma.rn.f32x2 %0, %1, %2, %0;" : "+l"(accum) : "l"(a64), "l"(b64))

__device__ __forceinline__ unsigned long long dup_f32(float v) {
    unsigned long long r;
    asm("mov.b64 %0, {%1, %1};" : "=l"(r) : "f"(v));
    return r;
}
__device__ __forceinline__ void unpack2(unsigned long long p, float &lo, float &hi) {
    asm("mov.b64 {%0, %1}, %2;" : "=f"(lo), "=f"(hi) : "l"(p));
}
__device__ __forceinline__ void cp16(uint32_t s, const void* g) {
    asm volatile("cp.async.cg.shared.global [%0], [%1], 16;" :: "r"(s), "l"(g));
}
__device__ __forceinline__ uint32_t pack_bf16x2(float lo, float hi) {
    uint32_t r;
    asm("cvt.rn.bf16x2.f32 %0, %1, %2;" : "=r"(r) : "f"(hi), "f"(lo));
    return r;
}
__device__ __forceinline__ void ldsm4(uint32_t* r, uint32_t addr) {
    asm volatile("ldmatrix.sync.aligned.m8n8.x4.shared.b16 {%0,%1,%2,%3}, [%4];"
                 : "=r"(r[0]), "=r"(r[1]), "=r"(r[2]), "=r"(r[3]) : "r"(addr));
}
__device__ __forceinline__ void ldsm2(uint32_t* r, uint32_t addr) {
    asm volatile("ldmatrix.sync.aligned.m8n8.x2.shared.b16 {%0,%1}, [%2];"
                 : "=r"(r[0]), "=r"(r[1]) : "r"(addr));
}
__device__ __forceinline__ void mma_bf16(float* c, const uint32_t* a,
                                         uint32_t b0, uint32_t b1) {
    asm volatile("mma.sync.aligned.m16n8k16.row.col.f32.bf16.bf16.f32 "
                 "{%0,%1,%2,%3}, {%4,%5,%6,%7}, {%8,%9}, {%0,%1,%2,%3};"
                 : "+f"(c[0]), "+f"(c[1]), "+f"(c[2]), "+f"(c[3])
                 : "r"(a[0]), "r"(a[1]), "r"(a[2]), "r"(a[3]), "r"(b0), "r"(b1));
}

// ---------------- Kernel 1: h = x @ W^T, stored (b,h,n,dh) ----------------
__global__ __launch_bounds__(128) void k1_proj(const float* __restrict__ x,
                                               const float* __restrict__ W) {
    __shared__ __align__(16) float sxt[128][20];
    __shared__ float sW[32][129];

    const int t = threadIdx.x;
    const int row0 = blockIdx.x * 16;
    const float* xb = x + (size_t)row0 * DD;
    const uint32_t sxt_addr = (uint32_t)__cvta_generic_to_shared(&sxt[0][0]);

    #pragma unroll
    for (int m = 0; m < 16; ++m) sxt[t][m] = xb[m * DD + t];

    unsigned long long acc[8];
    #pragma unroll
    for (int rp = 0; rp < 8; ++rp) acc[rp] = 0ull;

    for (int kt = 0; kt < DD; kt += 32) {
        __syncthreads();
        #pragma unroll
        for (int m = 0; m < 32; ++m) {
            int lin = t + 128 * m;
            int dp = lin >> 5, k = lin & 31;
            sW[k][dp] = W[dp * DD + kt + k];
        }
        __syncthreads();
        #pragma unroll
        for (int k = 0; k < 32; ++k) {
            unsigned long long wb = dup_f32(sW[k][t]);
            uint32_t ra = sxt_addr + (uint32_t)(kt + k) * 80u;
            unsigned long long x0, x1, x2, x3, x4, x5, x6, x7;
            asm("ld.shared.v2.b64 {%0,%1}, [%2];"    : "=l"(x0), "=l"(x1) : "r"(ra));
            asm("ld.shared.v2.b64 {%0,%1}, [%2+16];" : "=l"(x2), "=l"(x3) : "r"(ra));
            asm("ld.shared.v2.b64 {%0,%1}, [%2+32];" : "=l"(x4), "=l"(x5) : "r"(ra));
            asm("ld.shared.v2.b64 {%0,%1}, [%2+48];" : "=l"(x6), "=l"(x7) : "r"(ra));
            FFMA2(acc[0], x0, wb);
            FFMA2(acc[1], x1, wb);
            FFMA2(acc[2], x2, wb);
            FFMA2(acc[3], x3, wb);
            FFMA2(acc[4], x4, wb);
            FFMA2(acc[5], x5, wb);
            FFMA2(acc[6], x6, wb);
            FFMA2(acc[7], x7, wb);
        }
    }

    const int hh = t >> 5, dh = t & 31;
    #pragma unroll
    for (int rp = 0; rp < 8; ++rp) {
        float a0, a1;
        unpack2(acc[rp], a0, a1);
        int bn = row0 + 2 * rp;
        int b = bn >> 11, n = bn & 2047;
        size_t base = (((size_t)b * HH + hh) * NN + n) * DH + dh;
        g_h[base]      = a0;
        g_h[base + DH] = a1;
    }
}

// ---------------- Kernel 2: src/dst dots + exps ----------------
__global__ __launch_bounds__(256) void k2_srcdst(const float* __restrict__ a_src,
                                                 const float* __restrict__ a_dst) {
    int idx = blockIdx.x * 256 + threadIdx.x;
    int hh = (idx >> 11) & 3;
    const float* hrow = g_h + (size_t)idx * DH;
    const float* as = a_src + hh * DH;
    const float* ad = a_dst + hh * DH;
    float s = 0.f, d = 0.f;
    #pragma unroll
    for (int k = 0; k < DH; ++k) {
        float hv = hrow[k];
        s += hv * as[k];
        d += hv * ad[k];
    }
    g_src[idx] = s;
    g_dst[idx] = d;
    g_E [idx] = __expf(s);
    g_E5[idx] = __expf(0.2f * s);
    g_F [idx] = __expf(d);
    g_F5[idx] = __expf(0.2f * d);
}

// ---------------- Kernel 2b: build swizzled bf16 hi/lo B tiles ----------------
// B tile per (bh, jt): [NBP=40 rows][KT=64 cols] bf16, 128B rows, XOR-swizzled.
// rows 0..31: hT (B[n][k] = h[jt+k][n]); row 32: ones(hi)/zeros(lo); rows 33..39: 0.
__global__ __launch_bounds__(128) void k2b_btiles() {
    __shared__ float sh[64][33];
    const int bh = blockIdx.y, t = blockIdx.x, tid = threadIdx.x;
    const float* hsrc = g_h + ((size_t)bh * NN + t * KT) * DH;

    #pragma unroll
    for (int i = 0; i < 4; ++i) {
        int c = tid + 128 * i;                   // 0..511 float4s
        float4 v = ((const float4*)hsrc)[c];
        int k = c >> 3, n4 = c & 7;
        sh[k][n4 * 4 + 0] = v.x;
        sh[k][n4 * 4 + 1] = v.y;
        sh[k][n4 * 4 + 2] = v.z;
        sh[k][n4 * 4 + 3] = v.w;
    }
    __syncthreads();

    unsigned char* outhi = g_B + (size_t)(bh * NTILES + t) * BTILE_BYTES;
    unsigned char* outlo = outhi + BSPLIT_BYTES;

    #pragma unroll
    for (int i = 0; i < 3; ++i) {
        int ch = tid + 128 * i;                  // 16B chunk id, 0..319
        if (ch < 320) {
            int n = ch >> 3, c8 = ch & 7;
            uint32_t hiw[4], low[4];
            #pragma unroll
            for (int q = 0; q < 4; ++q) {
                float v0, v1;
                if (n < 32)      { v0 = sh[c8 * 8 + 2 * q][n]; v1 = sh[c8 * 8 + 2 * q + 1][n]; }
                else if (n == 32){ v0 = 1.f; v1 = 1.f; }
                else             { v0 = 0.f; v1 = 0.f; }
                uint32_t hw = pack_bf16x2(v0, v1);
                float f0 = __uint_as_float(hw << 16);
                float f1 = __uint_as_float(hw & 0xffff0000u);
                hiw[q] = hw;
                low[q] = (n < 32) ? pack_bf16x2(v0 - f0, v1 - f1) : 0u;
            }
            uint32_t off = (uint32_t)(n * 128 + (c8 * 16 ^ ((n & 7) << 4)));
            *(uint4*)(outhi + off) = make_uint4(hiw[0], hiw[1], hiw[2], hiw[3]);
            *(uint4*)(outlo + off) = make_uint4(low[0], low[1], low[2], low[3]);
        }
    }
}

// ---------------- Kernel 3: warp-MMA attention, pipelined ----------------
// grid (16, 32), block 256 (8 warps x 16 rows), 4 CTAs/SM (single wave).
// Per tile: ONE __syncthreads (publishes prefetched sB + guards buffer reuse);
// gen->MMA within a warp needs only __syncwarp (warp consumes its own A rows).
__global__ __launch_bounds__(256, 4) void k3_attn_tc(const float* __restrict__ adj) {
    extern __shared__ __align__(128) unsigned char dsm[];

    const int bh = blockIdx.y;
    const int i0 = blockIdx.x * MT;
    const int tid = threadIdx.x;
    const int warp = tid >> 5, lane = tid & 31;

    const uint32_t sb = (uint32_t)__cvta_generic_to_shared(dsm);
    const uint32_t sWhi_a = sb + SM_WHI;
    const uint32_t sWlo_a = sb + SM_WLO;
    const uint32_t sB_a   = sb + SM_SB;
    float* sh_rs  = (float*)(dsm + SM_RS);
    float* sh_rE  = (float*)(dsm + SM_RE);
    float* sh_rE5 = (float*)(dsm + SM_RE5);

    if (tid < MT) {
        int gi = bh * NN + i0 + tid;
        sh_rs [tid] = g_src[gi];
        sh_rE [tid] = g_E [gi];
        sh_rE5[tid] = g_E5[gi];
    }

    const int g0 = warp * 16;                 // this warp's 16 i-rows
    const int lr = lane & 7, lq = lane >> 3;
    const uint32_t xr = (uint32_t)lr << 4;    // swizzle term (row&7)<<4

    const uint32_t a_rowoff = (uint32_t)(g0 + lr + ((lq & 1) << 3)) * 128u;
    const uint32_t a_cbx = (uint32_t)(lq >> 1) << 4;
    const uint32_t b_rowadd = (uint32_t)(lr + ((lq >> 1) << 3));
    const uint32_t b_cbx = (uint32_t)(lq & 1) << 4;
    const uint32_t b2_cbx = (uint32_t)(lq & 1) << 4;   // x2: lanes 0..15 matter

    float c[5][4];
    #pragma unroll
    for (int nt = 0; nt < 5; ++nt)
        #pragma unroll
        for (int q = 0; q < 4; ++q) c[nt][q] = 0.f;

    const int jo = bh * NN;
    const unsigned char* gB0 = g_B + (size_t)(bh * NTILES) * BTILE_BYTES;

    // staging: 640 16B chunks per tile
    auto stage = [&](int buf, int t) {
        const unsigned char* gBt = gB0 + (size_t)t * BTILE_BYTES;
        const uint32_t dst = sB_a + (uint32_t)buf * BTILE_BYTES;
        #pragma unroll
        for (int i = 0; i < 3; ++i) {
            int idx = tid + 256 * i;
            if (idx < BTILE_BYTES / 16)
                cp16(dst + (uint32_t)idx * 16u, gBt + idx * 16);
        }
        asm volatile("cp.async.commit_group;");
    };

    stage(0, 0);                               // prefetch tile 0
    __syncthreads();                           // also publishes sh_rs

    for (int t = 0; t < NTILES; ++t) {
        asm volatile("cp.async.wait_group 0;");
        __syncthreads();   // publish sB[t&1]; all warps done with MMA(t-1)

        if (t + 1 < NTILES) stage((t + 1) & 1, t + 1);

        // --- gen phase: w(i,j) -> bf16 hi/lo into swizzled A rows (own warp) ---
        {
            const int jt = t * KT;
            const int jg = jo + jt + 2 * lane;
            const float2 dv  = *(const float2*)&g_dst[jg];
            const float2 Fv  = *(const float2*)&g_F [jg];
            const float2 F5v = *(const float2*)&g_F5[jg];
            const float* arow = adj + (size_t)(i0 + g0) * NN + jt + 2 * lane;

            #pragma unroll
            for (int r = 0; r < 16; ++r) {
                const int m = g0 + r;
                const float rs_m  = sh_rs[m];
                const float rE_m  = sh_rE[m];
                const float rE5_m = sh_rE5[m];
                const float2 av = *(const float2*)(arow + (size_t)r * NN);

                float s0 = rs_m + dv.x;
                float c0 = (s0 > 0.f) ? rE_m * Fv.x : rE5_m * F5v.x;
                float w0 = c0 * av.x;
                float s1 = rs_m + dv.y;
                float c1 = (s1 > 0.f) ? rE_m * Fv.y : rE5_m * F5v.y;
                float w1 = c1 * av.y;

                uint32_t hw = pack_bf16x2(w0, w1);
                float f0 = __uint_as_float(hw << 16);
                float f1 = __uint_as_float(hw & 0xffff0000u);
                uint32_t lw = pack_bf16x2(w0 - f0, w1 - f1);

                uint32_t off = (uint32_t)(m * 128 + ((lane * 4) ^ ((m & 7) << 4)));
                asm volatile("st.shared.b32 [%0], %1;" :: "r"(sWhi_a + off), "r"(hw) : "memory");
                asm volatile("st.shared.b32 [%0], %1;" :: "r"(sWlo_a + off), "r"(lw) : "memory");
            }
        }
        __syncwarp();      // gen -> ldmatrix within this warp

        // --- MMA phase: 4 k16-chunks x (2 n16 x4-tiles + 1 n8 x2-tile) ---
        const uint32_t bb = sB_a + (uint32_t)(t & 1) * BTILE_BYTES;
        #pragma unroll
        for (int ch = 0; ch < 4; ++ch) {
            const uint32_t cba = (uint32_t)(ch * 32) + a_cbx;
            uint32_t ahi[4], alo[4];
            ldsm4(ahi, sWhi_a + a_rowoff + (cba ^ xr));
            ldsm4(alo, sWlo_a + a_rowoff + (cba ^ xr));
            const uint32_t cbb = (uint32_t)(ch * 32) + b_cbx;
            #pragma unroll
            for (int p = 0; p < 2; ++p) {
                const uint32_t baddr = bb + (uint32_t)(p * 16 + b_rowadd) * 128u + (cbb ^ xr);
                uint32_t bh4[4];
                ldsm4(bh4, baddr);
                mma_bf16(c[2 * p],     ahi, bh4[0], bh4[1]);
                mma_bf16(c[2 * p],     alo, bh4[0], bh4[1]);
                mma_bf16(c[2 * p + 1], ahi, bh4[2], bh4[3]);
                mma_bf16(c[2 * p + 1], alo, bh4[2], bh4[3]);
                uint32_t bl4[4];
                ldsm4(bl4, baddr + BSPLIT_BYTES);
                mma_bf16(c[2 * p],     ahi, bl4[0], bl4[1]);
                mma_bf16(c[2 * p + 1], ahi, bl4[2], bl4[3]);
            }
            // n-tile 4 (rows 32..39: ones col 32; lo of ones row is 0 -> skip Blo)
            const uint32_t cb2 = (uint32_t)(ch * 32) + b2_cbx;
            const uint32_t baddr2 = bb + (uint32_t)(32 + lr) * 128u + (cb2 ^ xr);
            uint32_t b2[2];
            ldsm2(b2, baddr2);
            mma_bf16(c[4], ahi, b2[0], b2[1]);
            mma_bf16(c[4], alo, b2[0], b2[1]);
        }
    }

    // --- epilogue: row sums from col 32 (tile 4), normalize, store ---
    const float s_lo = __shfl_sync(0xffffffffu, c[4][0], lane & ~3);
    const float s_hi = __shfl_sync(0xffffffffu, c[4][2], lane & ~3);
    const float r0 = 1.0f / s_lo;
    const float r1 = 1.0f / s_hi;

    const int b = bh >> 2, hh = bh & 3;
    const int ia = i0 + g0 + (lane >> 2);
    float* dst0 = g_att + ((size_t)b * NN + ia) * DD + hh * DH + 2 * (lane & 3);
    float* dst1 = dst0 + 8 * (size_t)DD;   // row ia+8
    #pragma unroll
    for (int nt = 0; nt < 4; ++nt) {
        *(float2*)(dst0 + nt * 8) = make_float2(c[nt][0] * r0, c[nt][1] * r0);
        *(float2*)(dst1 + nt * 8) = make_float2(c[nt][2] * r1, c[nt][3] * r1);
    }
}

// ---------------- Kernel 4: out = att @ Wo^T + bo; y = x + out; LayerNorm ----
__global__ __launch_bounds__(128) void k4_proj_ln(const float* __restrict__ x,
                                                  const float* __restrict__ Wo,
                                                  const float* __restrict__ bo,
                                                  const float* __restrict__ gamma,
                                                  const float* __restrict__ beta,
                                                  float* __restrict__ out) {
    __shared__ __align__(16) float sat[128][20];
    __shared__ float sW[32][129];
    __shared__ float sy[16][128];
    __shared__ float smu[16], srstd[16];

    const int t = threadIdx.x;
    const int row0 = blockIdx.x * 16;
    const float* ab = g_att + (size_t)row0 * DD;
    const uint32_t sat_addr = (uint32_t)__cvta_generic_to_shared(&sat[0][0]);

    #pragma unroll
    for (int m = 0; m < 16; ++m) sat[t][m] = ab[m * DD + t];

    unsigned long long acc[8];
    #pragma unroll
    for (int rp = 0; rp < 8; ++rp) acc[rp] = 0ull;

    for (int kt = 0; kt < DD; kt += 32) {
        __syncthreads();
        #pragma unroll
        for (int m = 0; m < 32; ++m) {
            int lin = t + 128 * m;
            int dp = lin >> 5, k = lin & 31;
            sW[k][dp] = Wo[dp * DD + kt + k];
        }
        __syncthreads();
        #pragma unroll
        for (int k = 0; k < 32; ++k) {
            unsigned long long wb = dup_f32(sW[k][t]);
            uint32_t ra = sat_addr + (uint32_t)(kt + k) * 80u;
            unsigned long long x0, x1, x2, x3, x4, x5, x6, x7;
            asm("ld.shared.v2.b64 {%0,%1}, [%2];"    : "=l"(x0), "=l"(x1) : "r"(ra));
            asm("ld.shared.v2.b64 {%0,%1}, [%2+16];" : "=l"(x2), "=l"(x3) : "r"(ra));
            asm("ld.shared.v2.b64 {%0,%1}, [%2+32];" : "=l"(x4), "=l"(x5) : "r"(ra));
            asm("ld.shared.v2.b64 {%0,%1}, [%2+48];" : "=l"(x6), "=l"(x7) : "r"(ra));
            FFMA2(acc[0], x0, wb);
            FFMA2(acc[1], x1, wb);
            FFMA2(acc[2], x2, wb);
            FFMA2(acc[3], x3, wb);
            FFMA2(acc[4], x4, wb);
            FFMA2(acc[5], x5, wb);
            FFMA2(acc[6], x6, wb);
            FFMA2(acc[7], x7, wb);
        }
    }
    __syncthreads();

    const float bov = bo[t];
    float yv[16];
    #pragma unroll
    for (int rp = 0; rp < 8; ++rp) {
        int r0 = 2 * rp;
        float a0, a1;
        unpack2(acc[rp], a0, a1);
        float y0 = x[(size_t)(row0 + r0) * DD + t]     + a0 + bov;
        float y1 = x[(size_t)(row0 + r0 + 1) * DD + t] + a1 + bov;
        yv[r0] = y0; yv[r0 + 1] = y1;
        sy[r0][t] = y0; sy[r0 + 1][t] = y1;
    }
    __syncthreads();

    {
        int w = t >> 5, lane = t & 31;
        #pragma unroll
        for (int rr = 0; rr < 4; ++rr) {
            int r = w * 4 + rr;
            float s = 0.f, q = 0.f;
            #pragma unroll
            for (int cc = 0; cc < 4; ++cc) {
                float v = sy[r][lane + 32 * cc];
                s += v;
                q += v * v;
            }
            #pragma unroll
            for (int off = 16; off > 0; off >>= 1) {
                s += __shfl_xor_sync(0xffffffffu, s, off);
                q += __shfl_xor_sync(0xffffffffu, q, off);
            }
            if (lane == 0) {
                float mu = s * (1.0f / DD);
                float var = q * (1.0f / DD) - mu * mu;
                smu[r] = mu;
                srstd[r] = rsqrtf(var + 1e-5f);
            }
        }
    }
    __syncthreads();

    const float gv = gamma[t], bev = beta[t];
    #pragma unroll
    for (int r = 0; r < 16; ++r) {
        out[(size_t)(row0 + r) * DD + t] = (yv[r] - smu[r]) * srstd[r] * gv + bev;
    }
}

// ---------------- launch ----------------
extern "C" void kernel_launch(void* const* d_in, const int* in_sizes, int n_in,
                              void* d_out, int out_size) {
    const float* x     = (const float*)d_in[0];
    const float* adj   = (const float*)d_in[1];
    const float* W     = (const float*)d_in[2];
    const float* a_src = (const float*)d_in[3];
    const float* a_dst = (const float*)d_in[4];
    const float* Wo    = (const float*)d_in[5];
    const float* bo    = (const float*)d_in[6];
    const float* gamma = (const float*)d_in[7];
    const float* beta  = (const float*)d_in[8];
    float* out = (float*)d_out;

    cudaFuncSetAttribute(k3_attn_tc, cudaFuncAttributeMaxDynamicSharedMemorySize, SM_TOTAL);

    k1_proj<<<BN / 16, 128>>>(x, W);
    k2_srcdst<<<(NBH * NN) / 256, 256>>>(a_src, a_dst);
    k2b_btiles<<<dim3(NTILES, NBH), 128>>>();
    k3_attn_tc<<<dim3(NN / MT, NBH), 256, SM_TOTAL>>>(adj);
    k4_proj_ln<<<BN / 16, 128>>>(x, Wo, bo, gamma, beta, out);
}